// round 1
// baseline (speedup 1.0000x reference)
#include <cuda_runtime.h>

#define NCAT 20
#define NNUM 20
#define EMBD 32
#define HID  128
#define NMOD 50
#define TILE 32

// ---------------- device scratch (no allocations allowed) ----------------
__device__ float g_Tcat[NCAT * NMOD * HID];   // folded cat-embedding @ W_in   (512 KB)
__device__ float g_A[3 * HID * HID];          // A1 = W1_0@W2_0 ; A2 = diag(g1)(W1_1@W2_1) ; A3 = diag(g2) W_out
__device__ float g_vnum[NNUM * HID];          // W_num[f] @ W_in block
__device__ float g_base[HID];                 // b_in + b_num folded
__device__ float g_d[3 * HID];                // folded bias vectors per stage

// ---------------- precompute kernels ----------------
__global__ void pre_tcat_kernel(const float* __restrict__ emb,
                                const float* __restrict__ W_in) {
    int fc = blockIdx.x;          // f*50 + c, 0..999
    int f  = fc / NMOD;
    int j  = threadIdx.x;
    const float* e = emb + fc * EMBD;
    float s = 0.f;
#pragma unroll
    for (int k = 0; k < EMBD; k++)
        s += e[k] * W_in[(f * EMBD + k) * HID + j];
    g_Tcat[fc * HID + j] = s;
}

__global__ void pre_A_kernel(const float* __restrict__ W1, const float* __restrict__ W2,
                             const float* __restrict__ ln_g, const float* __restrict__ W_out) {
    int bx = blockIdx.x;          // 0..383 : s = bx>>7, k = bx&127
    int s = bx >> 7, k = bx & 127, j = threadIdx.x;
    float v;
    if (s == 2) {
        v = ln_g[HID + k] * W_out[k * HID + j];
    } else {
        const float* w1 = W1 + s * HID * 2 * HID + k * 2 * HID;
        const float* w2 = W2 + s * 2 * HID * HID;
        float acc = 0.f;
        for (int m = 0; m < 2 * HID; m++) acc += w1[m] * w2[m * HID + j];
        v = (s == 1) ? ln_g[k] * acc : acc;
    }
    g_A[bx * HID + j] = v;
}

__global__ void pre_vec_kernel(const float* __restrict__ W_num, const float* __restrict__ b_num,
                               const float* __restrict__ W_in,  const float* __restrict__ b_in,
                               const float* __restrict__ W1,    const float* __restrict__ b1,
                               const float* __restrict__ W2,    const float* __restrict__ b2,
                               const float* __restrict__ ln_g,  const float* __restrict__ ln_b,
                               const float* __restrict__ W_out, const float* __restrict__ b_out) {
    int j = threadIdx.x;          // 0..127, single block
    // v_num[f][j] = W_num[f] . W_in block(20+f)
    for (int f = 0; f < NNUM; f++) {
        float s = 0.f;
#pragma unroll
        for (int k = 0; k < EMBD; k++)
            s += W_num[f * EMBD + k] * W_in[((NCAT + f) * EMBD + k) * HID + j];
        g_vnum[f * HID + j] = s;
    }
    // base = b_in + sum_f b_num[f] @ W_in block
    float b = b_in[j];
    for (int f = 0; f < NNUM; f++)
#pragma unroll
        for (int k = 0; k < EMBD; k++)
            b += b_num[f * EMBD + k] * W_in[((NCAT + f) * EMBD + k) * HID + j];
    g_base[j] = b;
    // d1 = b1[0] @ W2[0] + b2[0]
    float d1 = b2[j];
    for (int m = 0; m < 2 * HID; m++) d1 += b1[m] * W2[m * HID + j];
    g_d[j] = d1;
    // d2 = ln_b[0] @ (W1[1]@W2[1]) + b1[1]@W2[1] + b2[1]
    __shared__ float u[2 * HID];  // u[m] = sum_k ln_b0[k] * W1[1][k][m]
    for (int m = j; m < 2 * HID; m += HID) {
        float s = 0.f;
        for (int k = 0; k < HID; k++)
            s += ln_b[k] * W1[HID * 2 * HID + k * 2 * HID + m];
        u[m] = s;
    }
    __syncthreads();
    float d2 = b2[HID + j];
    for (int m = 0; m < 2 * HID; m++)
        d2 += (u[m] + b1[2 * HID + m]) * W2[2 * HID * HID + m * HID + j];
    g_d[HID + j] = d2;
    // d3 = ln_b[1] @ W_out + b_out
    float d3 = b_out[j];
    for (int k = 0; k < HID; k++) d3 += ln_b[HID + k] * W_out[k * HID + j];
    g_d[2 * HID + j] = d3;
}

// ---------------- main fused kernel ----------------
// Dynamic smem layout (floats):
//   A_s   [3*128*128] = 49152
//   ht    [128*32]    =  4096   (transposed h: ht[k*32+r])
//   xs    [32*40]     =  1280
//   p1    [128], p2 [128], mu [32], rs [32]
#define SM_A  0
#define SM_HT (3 * HID * HID)
#define SM_XS (SM_HT + HID * TILE)
#define SM_P1 (SM_XS + TILE * 40)
#define SM_P2 (SM_P1 + 128)
#define SM_MU (SM_P2 + 128)
#define SM_RS (SM_MU + 32)
#define SM_TOTAL (SM_RS + 32)

__global__ __launch_bounds__(128, 1)
void main_kernel(const float* __restrict__ x, float* __restrict__ out,
                 int nrows, int ntiles) {
    extern __shared__ float sm[];
    float* A_s = sm + SM_A;
    float* ht  = sm + SM_HT;
    float* xs  = sm + SM_XS;
    float* p1  = sm + SM_P1;
    float* p2  = sm + SM_P2;
    float* mus = sm + SM_MU;
    float* rss = sm + SM_RS;

    const int j = threadIdx.x;

    // load the 3 folded matrices once per CTA (float4)
    {
        const float4* src = (const float4*)g_A;
        float4* dst = (float4*)A_s;
        for (int i = j; i < 3 * HID * HID / 4; i += 128) dst[i] = src[i];
    }
    __syncthreads();

    for (int t = blockIdx.x; t < ntiles; t += gridDim.x) {
        const int row0 = t * TILE;
        // stage x tile into smem (guard tail)
        for (int i = j; i < TILE * 40; i += 128) {
            int r = i / 40;
            xs[i] = (row0 + r < nrows) ? x[row0 * 40 + i] : 0.f;
        }
        __syncthreads();

        // embedding + folded W_in: thread j produces column j of h1 for all rows
        {
            const float bj = g_base[j];
#pragma unroll 2
            for (int r = 0; r < TILE; r++) {
                const float* xr = xs + r * 40;
                float v = bj;
#pragma unroll
                for (int f = 0; f < NCAT; f++) {
                    int idx = (int)xr[f];
                    v += g_Tcat[(f * NMOD + idx) * HID + j];
                }
#pragma unroll
                for (int f = 0; f < NNUM; f++)
                    v += xr[NCAT + f] * g_vnum[f * HID + j];
                ht[j * TILE + r] = v;
            }
        }
        __syncthreads();

        float acc[TILE];
#pragma unroll 1
        for (int s = 0; s < 3; s++) {
            const float dj = g_d[s * HID + j];
#pragma unroll
            for (int r = 0; r < TILE; r++) acc[r] = dj;

            const float*  As = A_s + s * HID * HID;
            const float4* h4 = (const float4*)ht;
#pragma unroll 2
            for (int k = 0; k < HID; k++) {
                const float a = As[k * HID + j];
#pragma unroll
                for (int q = 0; q < TILE / 4; q++) {
                    float4 h = h4[k * (TILE / 4) + q];
                    acc[q * 4 + 0] += h.x * a;
                    acc[q * 4 + 1] += h.y * a;
                    acc[q * 4 + 2] += h.z * a;
                    acc[q * 4 + 3] += h.w * a;
                }
            }

            if (s == 2) {
                // final stage: write output (coalesced across j)
#pragma unroll
                for (int r = 0; r < TILE; r++)
                    if (row0 + r < nrows)
                        out[(size_t)(row0 + r) * HID + j] = acc[r];
                __syncthreads();   // protect ht/xs before next tile
            } else {
                __syncthreads();   // all reads of old ht done
                // write raw pre-LN values back (transposed)
                {
                    float4* hw = (float4*)ht;
#pragma unroll
                    for (int q = 0; q < TILE / 4; q++)
                        hw[j * (TILE / 4) + q] =
                            make_float4(acc[q * 4 + 0], acc[q * 4 + 1],
                                        acc[q * 4 + 2], acc[q * 4 + 3]);
                }
                __syncthreads();
                // LN stats: 4 partials per row
                {
                    int r = j & 31, p = j >> 5;
                    float s1 = 0.f, s2 = 0.f;
                    for (int k = p * 32; k < p * 32 + 32; k++) {
                        float v = ht[k * TILE + r];
                        s1 += v;
                        s2 += v * v;
                    }
                    p1[p * 32 + r] = s1;
                    p2[p * 32 + r] = s2;
                }
                __syncthreads();
                if (j < 32) {
                    float m  = p1[j] + p1[32 + j] + p1[64 + j] + p1[96 + j];
                    float q2 = p2[j] + p2[32 + j] + p2[64 + j] + p2[96 + j];
                    m *= (1.f / HID);
                    float var = q2 * (1.f / HID) - m * m;
                    mus[j] = m;
                    rss[j] = rsqrtf(var + 1e-5f);
                }
                __syncthreads();
                // normalize from registers, store back
                {
                    float4* hw = (float4*)ht;
#pragma unroll
                    for (int q = 0; q < TILE / 4; q++) {
                        float4 hv;
                        hv.x = (acc[q * 4 + 0] - mus[q * 4 + 0]) * rss[q * 4 + 0];
                        hv.y = (acc[q * 4 + 1] - mus[q * 4 + 1]) * rss[q * 4 + 1];
                        hv.z = (acc[q * 4 + 2] - mus[q * 4 + 2]) * rss[q * 4 + 2];
                        hv.w = (acc[q * 4 + 3] - mus[q * 4 + 3]) * rss[q * 4 + 3];
                        hw[j * (TILE / 4) + q] = hv;
                    }
                }
                __syncthreads();
            }
        }
    }
}

// ---------------- launch ----------------
extern "C" void kernel_launch(void* const* d_in, const int* in_sizes, int n_in,
                              void* d_out, int out_size) {
    const float* x     = (const float*)d_in[0];
    const float* emb   = (const float*)d_in[1];
    const float* W_num = (const float*)d_in[2];
    const float* b_num = (const float*)d_in[3];
    const float* W_in  = (const float*)d_in[4];
    const float* b_in  = (const float*)d_in[5];
    const float* W1    = (const float*)d_in[6];
    const float* b1    = (const float*)d_in[7];
    const float* W2    = (const float*)d_in[8];
    const float* b2    = (const float*)d_in[9];
    const float* ln_g  = (const float*)d_in[10];
    const float* ln_b  = (const float*)d_in[11];
    const float* W_out = (const float*)d_in[12];
    const float* b_out = (const float*)d_in[13];
    float* out = (float*)d_out;

    const int nrows  = in_sizes[0] / 40;
    const int ntiles = (nrows + TILE - 1) / TILE;

    static int smem_set = 0;
    if (!smem_set) {
        cudaFuncSetAttribute(main_kernel, cudaFuncAttributeMaxDynamicSharedMemorySize,
                             SM_TOTAL * (int)sizeof(float));
        smem_set = 1;
    }

    pre_tcat_kernel<<<NCAT * NMOD, HID>>>(emb, W_in);
    pre_A_kernel<<<3 * HID, HID>>>(W1, W2, ln_g, W_out);
    pre_vec_kernel<<<1, HID>>>(W_num, b_num, W_in, b_in, W1, b1, W2, b2,
                               ln_g, ln_b, W_out, b_out);
    main_kernel<<<148, HID, SM_TOTAL * (int)sizeof(float)>>>(x, out, nrows, ntiles);
}

// round 2
// speedup vs baseline: 1.5558x; 1.5558x over previous
#include <cuda_runtime.h>

#define NCAT 20
#define NNUM 20
#define EMBD 32
#define HID  128
#define NMOD 50
#define TILE 32
#define NTHR 512   // 16 warps, 4/SMSP

// ---------------- device scratch ----------------
__device__ float g_Tcat[NCAT * NMOD * HID];   // folded cat-embedding @ W_in (512 KB)
__device__ float g_A[3 * HID * HID];          // folded 128x128 stage matrices
__device__ float g_vnum[NNUM * HID];
__device__ float g_base[HID];
__device__ float g_d[3 * HID];

// ---------------- precompute kernels ----------------
__global__ void pre_tcat_kernel(const float* __restrict__ emb,
                                const float* __restrict__ W_in) {
    int fc = blockIdx.x, f = fc / NMOD, j = threadIdx.x;
    const float* e = emb + fc * EMBD;
    float s = 0.f;
#pragma unroll
    for (int k = 0; k < EMBD; k++)
        s += e[k] * W_in[(f * EMBD + k) * HID + j];
    g_Tcat[fc * HID + j] = s;
}

__global__ void pre_A_kernel(const float* __restrict__ W1, const float* __restrict__ W2,
                             const float* __restrict__ ln_g, const float* __restrict__ W_out) {
    int bx = blockIdx.x;
    int s = bx >> 7, k = bx & 127, j = threadIdx.x;
    float v;
    if (s == 2) {
        v = ln_g[HID + k] * W_out[k * HID + j];
    } else {
        const float* w1 = W1 + s * HID * 2 * HID + k * 2 * HID;
        const float* w2 = W2 + s * 2 * HID * HID;
        float acc = 0.f;
        for (int m = 0; m < 2 * HID; m++) acc += w1[m] * w2[m * HID + j];
        v = (s == 1) ? ln_g[k] * acc : acc;
    }
    g_A[bx * HID + j] = v;
}

__global__ void pre_vec_kernel(const float* __restrict__ W_num, const float* __restrict__ b_num,
                               const float* __restrict__ W_in,  const float* __restrict__ b_in,
                               const float* __restrict__ W1,    const float* __restrict__ b1,
                               const float* __restrict__ W2,    const float* __restrict__ b2,
                               const float* __restrict__ ln_g,  const float* __restrict__ ln_b,
                               const float* __restrict__ W_out, const float* __restrict__ b_out) {
    int j = threadIdx.x;
    for (int f = 0; f < NNUM; f++) {
        float s = 0.f;
#pragma unroll
        for (int k = 0; k < EMBD; k++)
            s += W_num[f * EMBD + k] * W_in[((NCAT + f) * EMBD + k) * HID + j];
        g_vnum[f * HID + j] = s;
    }
    float b = b_in[j];
    for (int f = 0; f < NNUM; f++)
#pragma unroll
        for (int k = 0; k < EMBD; k++)
            b += b_num[f * EMBD + k] * W_in[((NCAT + f) * EMBD + k) * HID + j];
    g_base[j] = b;
    float d1 = b2[j];
    for (int m = 0; m < 2 * HID; m++) d1 += b1[m] * W2[m * HID + j];
    g_d[j] = d1;
    __shared__ float u[2 * HID];
    for (int m = j; m < 2 * HID; m += HID) {
        float s = 0.f;
        for (int k = 0; k < HID; k++)
            s += ln_b[k] * W1[HID * 2 * HID + k * 2 * HID + m];
        u[m] = s;
    }
    __syncthreads();
    float d2 = b2[HID + j];
    for (int m = 0; m < 2 * HID; m++)
        d2 += (u[m] + b1[2 * HID + m]) * W2[2 * HID * HID + m * HID + j];
    g_d[HID + j] = d2;
    float d3 = b_out[j];
    for (int k = 0; k < HID; k++) d3 += ln_b[HID + k] * W_out[k * HID + j];
    g_d[2 * HID + j] = d3;
}

// ---------------- main fused kernel ----------------
// smem layout (floats)
#define SM_A  0
#define SM_HT (3 * HID * HID)            // 49152
#define SM_XS (SM_HT + HID * TILE)       // 53248
#define SM_P1 (SM_XS + TILE * 40)        // 54528
#define SM_P2 (SM_P1 + 16 * TILE)        // 55040
#define SM_MU (SM_P2 + 16 * TILE)        // 55552
#define SM_RS (SM_MU + TILE)             // 55584
#define SM_TOTAL (SM_RS + TILE)          // 55616 floats = 222464 B

__global__ __launch_bounds__(NTHR, 1)
void main_kernel(const float* __restrict__ x, float* __restrict__ out,
                 int nrows, int ntiles) {
    extern __shared__ float sm[];
    float* A_s = sm + SM_A;
    float* ht  = sm + SM_HT;
    float* xs  = sm + SM_XS;
    float* p1  = sm + SM_P1;
    float* p2  = sm + SM_P2;
    float* mus = sm + SM_MU;
    float* rss = sm + SM_RS;

    const int t  = threadIdx.x;
    const int j  = t & (HID - 1);   // column 0..127
    const int rg = t >> 7;          // row group 0..3
    const int r0 = rg * 8;          // first of this thread's 8 rows

    // load folded matrices once per CTA
    {
        const float4* src = (const float4*)g_A;
        float4* dst = (float4*)A_s;
        for (int i = t; i < 3 * HID * HID / 4; i += NTHR) dst[i] = src[i];
    }

    // hoist per-thread invariants
    const float bj = g_base[j];
    float vn[NNUM];
#pragma unroll
    for (int f = 0; f < NNUM; f++) vn[f] = g_vnum[f * HID + j];
    const float d0 = g_d[j], d1v = g_d[HID + j], d2v = g_d[2 * HID + j];

    __syncthreads();

    for (int tt = blockIdx.x; tt < ntiles; tt += gridDim.x) {
        const int row0 = tt * TILE;
        // stage x tile into smem
        for (int i = t; i < TILE * 40; i += NTHR) {
            int r = i / 40;
            xs[i] = (row0 + r < nrows) ? x[row0 * 40 + i] : 0.f;
        }
        __syncthreads();

        // embedding + folded W_in: thread (j, rg) fills ht[j][r0..r0+7]
#pragma unroll 2
        for (int i = 0; i < 8; i++) {
            const float* xr = xs + (r0 + i) * 40;
            float v = bj;
#pragma unroll
            for (int f = 0; f < NCAT; f++) {
                int idx = (int)xr[f];
                v += g_Tcat[(f * NMOD + idx) * HID + j];
            }
#pragma unroll
            for (int f = 0; f < NNUM; f++)
                v += xr[NCAT + f] * vn[f];
            ht[j * TILE + r0 + i] = v;
        }
        __syncthreads();

        float acc[8];
#pragma unroll 1
        for (int s = 0; s < 3; s++) {
            const float dj = (s == 0) ? d0 : (s == 1) ? d1v : d2v;
#pragma unroll
            for (int i = 0; i < 8; i++) acc[i] = dj;

            const float*  As = A_s + s * HID * HID;
            const float4* h4 = (const float4*)ht;
#pragma unroll 4
            for (int k = 0; k < HID; k++) {
                const float a = As[k * HID + j];
                float4 h0 = h4[k * (TILE / 4) + rg * 2 + 0];
                float4 h1 = h4[k * (TILE / 4) + rg * 2 + 1];
                acc[0] += h0.x * a;  acc[1] += h0.y * a;
                acc[2] += h0.z * a;  acc[3] += h0.w * a;
                acc[4] += h1.x * a;  acc[5] += h1.y * a;
                acc[6] += h1.z * a;  acc[7] += h1.w * a;
            }

            if (s == 2) {
#pragma unroll
                for (int i = 0; i < 8; i++)
                    if (row0 + r0 + i < nrows)
                        out[(size_t)(row0 + r0 + i) * HID + j] = acc[i];
                __syncthreads();   // protect ht/xs before next tile
            } else {
                __syncthreads();   // all reads of old ht done
                // write raw pre-LN values (transposed ht[col][row])
                {
                    float4* hw = (float4*)ht;
                    hw[j * (TILE / 4) + rg * 2 + 0] =
                        make_float4(acc[0], acc[1], acc[2], acc[3]);
                    hw[j * (TILE / 4) + rg * 2 + 1] =
                        make_float4(acc[4], acc[5], acc[6], acc[7]);
                }
                __syncthreads();
                // LN stats: 16 partials per row (8 k-values each)
                {
                    int r = t & 31, p = t >> 5;
                    float s1 = 0.f, s2 = 0.f;
#pragma unroll
                    for (int k = p * 8; k < p * 8 + 8; k++) {
                        float v = ht[k * TILE + r];
                        s1 += v;
                        s2 += v * v;
                    }
                    p1[p * TILE + r] = s1;
                    p2[p * TILE + r] = s2;
                }
                __syncthreads();
                if (t < TILE) {
                    float m = 0.f, q2 = 0.f;
#pragma unroll
                    for (int p = 0; p < 16; p++) {
                        m  += p1[p * TILE + t];
                        q2 += p2[p * TILE + t];
                    }
                    m *= (1.f / HID);
                    float var = q2 * (1.f / HID) - m * m;
                    mus[t] = m;
                    rss[t] = rsqrtf(var + 1e-5f);
                }
                __syncthreads();
                // normalize from registers, store back
                {
                    float4* hw = (float4*)ht;
                    float4 a0, a1;
                    a0.x = (acc[0] - mus[r0 + 0]) * rss[r0 + 0];
                    a0.y = (acc[1] - mus[r0 + 1]) * rss[r0 + 1];
                    a0.z = (acc[2] - mus[r0 + 2]) * rss[r0 + 2];
                    a0.w = (acc[3] - mus[r0 + 3]) * rss[r0 + 3];
                    a1.x = (acc[4] - mus[r0 + 4]) * rss[r0 + 4];
                    a1.y = (acc[5] - mus[r0 + 5]) * rss[r0 + 5];
                    a1.z = (acc[6] - mus[r0 + 6]) * rss[r0 + 6];
                    a1.w = (acc[7] - mus[r0 + 7]) * rss[r0 + 7];
                    hw[j * (TILE / 4) + rg * 2 + 0] = a0;
                    hw[j * (TILE / 4) + rg * 2 + 1] = a1;
                }
                __syncthreads();
            }
        }
    }
}

// ---------------- launch ----------------
extern "C" void kernel_launch(void* const* d_in, const int* in_sizes, int n_in,
                              void* d_out, int out_size) {
    const float* x     = (const float*)d_in[0];
    const float* emb   = (const float*)d_in[1];
    const float* W_num = (const float*)d_in[2];
    const float* b_num = (const float*)d_in[3];
    const float* W_in  = (const float*)d_in[4];
    const float* b_in  = (const float*)d_in[5];
    const float* W1    = (const float*)d_in[6];
    const float* b1    = (const float*)d_in[7];
    const float* W2    = (const float*)d_in[8];
    const float* b2    = (const float*)d_in[9];
    const float* ln_g  = (const float*)d_in[10];
    const float* ln_b  = (const float*)d_in[11];
    const float* W_out = (const float*)d_in[12];
    const float* b_out = (const float*)d_in[13];
    float* out = (float*)d_out;

    const int nrows  = in_sizes[0] / 40;
    const int ntiles = (nrows + TILE - 1) / TILE;

    static int smem_set = 0;
    if (!smem_set) {
        cudaFuncSetAttribute(main_kernel, cudaFuncAttributeMaxDynamicSharedMemorySize,
                             SM_TOTAL * (int)sizeof(float));
        smem_set = 1;
    }

    pre_tcat_kernel<<<NCAT * NMOD, HID>>>(emb, W_in);
    pre_A_kernel<<<3 * HID, HID>>>(W1, W2, ln_g, W_out);
    pre_vec_kernel<<<1, HID>>>(W_num, b_num, W_in, b_in, W1, b1, W2, b2,
                               ln_g, ln_b, W_out, b_out);
    main_kernel<<<148, NTHR, SM_TOTAL * (int)sizeof(float)>>>(x, out, nrows, ntiles);
}

// round 3
// speedup vs baseline: 2.4697x; 1.5874x over previous
#include <cuda_runtime.h>

#define NCAT 20
#define NNUM 20
#define EMBD 32
#define HID  128
#define NMOD 50
#define TILE 64            // rows per CTA tile
#define NTHR 512           // 16 warps; warp w owns rows 4w..4w+3; lane l owns cols 4l..4l+3

// ---------------- device scratch ----------------
__device__ float g_Tcat[NCAT * NMOD * HID];   // folded cat-embedding @ W_in (512 KB)
__device__ float g_A[3 * HID * HID];          // folded 128x128 stage matrices
__device__ float g_vnum[NNUM * HID];
__device__ float g_base[HID];
__device__ float g_d[3 * HID];

// ---------------- precompute kernels ----------------
__global__ void pre_tcat_kernel(const float* __restrict__ emb,
                                const float* __restrict__ W_in) {
    int fc = blockIdx.x, f = fc / NMOD, j = threadIdx.x;
    const float* e = emb + fc * EMBD;
    float s = 0.f;
#pragma unroll
    for (int k = 0; k < EMBD; k++)
        s += e[k] * W_in[(f * EMBD + k) * HID + j];
    g_Tcat[fc * HID + j] = s;
}

__global__ void pre_A_kernel(const float* __restrict__ W1, const float* __restrict__ W2,
                             const float* __restrict__ ln_g, const float* __restrict__ W_out) {
    int bx = blockIdx.x;
    int s = bx >> 7, k = bx & 127, j = threadIdx.x;
    float v;
    if (s == 2) {
        v = ln_g[HID + k] * W_out[k * HID + j];
    } else {
        const float* w1 = W1 + s * HID * 2 * HID + k * 2 * HID;
        const float* w2 = W2 + s * 2 * HID * HID;
        float acc = 0.f;
        for (int m = 0; m < 2 * HID; m++) acc += w1[m] * w2[m * HID + j];
        v = (s == 1) ? ln_g[k] * acc : acc;
    }
    g_A[bx * HID + j] = v;
}

__global__ void pre_vec_kernel(const float* __restrict__ W_num, const float* __restrict__ b_num,
                               const float* __restrict__ W_in,  const float* __restrict__ b_in,
                               const float* __restrict__ W1,    const float* __restrict__ b1,
                               const float* __restrict__ W2,    const float* __restrict__ b2,
                               const float* __restrict__ ln_g,  const float* __restrict__ ln_b,
                               const float* __restrict__ W_out, const float* __restrict__ b_out) {
    int j = threadIdx.x;
    for (int f = 0; f < NNUM; f++) {
        float s = 0.f;
#pragma unroll
        for (int k = 0; k < EMBD; k++)
            s += W_num[f * EMBD + k] * W_in[((NCAT + f) * EMBD + k) * HID + j];
        g_vnum[f * HID + j] = s;
    }
    float b = b_in[j];
    for (int f = 0; f < NNUM; f++)
#pragma unroll
        for (int k = 0; k < EMBD; k++)
            b += b_num[f * EMBD + k] * W_in[((NCAT + f) * EMBD + k) * HID + j];
    g_base[j] = b;
    float d1 = b2[j];
    for (int m = 0; m < 2 * HID; m++) d1 += b1[m] * W2[m * HID + j];
    g_d[j] = d1;
    __shared__ float u[2 * HID];
    for (int m = j; m < 2 * HID; m += HID) {
        float s = 0.f;
        for (int k = 0; k < HID; k++)
            s += ln_b[k] * W1[HID * 2 * HID + k * 2 * HID + m];
        u[m] = s;
    }
    __syncthreads();
    float d2 = b2[HID + j];
    for (int m = 0; m < 2 * HID; m++)
        d2 += (u[m] + b1[2 * HID + m]) * W2[2 * HID * HID + m * HID + j];
    g_d[HID + j] = d2;
    float d3 = b_out[j];
    for (int k = 0; k < HID; k++) d3 += ln_b[HID + k] * W_out[k * HID + j];
    g_d[2 * HID + j] = d3;
}

// ---------------- main fused kernel ----------------
// smem: A (3*128*128 floats = 192KB) then per-warp h regions:
//   ht_w[k] = float4 holding h[rows 4w..4w+3][k], k = 0..127  (2KB per warp, 32KB total)
#define SM_A   0
#define SM_HT  (3 * HID * HID)            // 49152 floats
#define SM_TOTALF (SM_HT + 16 * HID * 4)  // + 8192 floats -> 57344 floats = 229376 B

__global__ __launch_bounds__(NTHR, 1)
void main_kernel(const float* __restrict__ x, float* __restrict__ out,
                 int nrows, int ntiles) {
    extern __shared__ float sm[];
    const int t = threadIdx.x;
    const int l = t & 31;          // lane: cols 4l..4l+3
    const int w = t >> 5;          // warp: rows 4w..4w+3 within tile

    float4* htw = (float4*)(sm + SM_HT) + w * HID;   // this warp's 128 float4s

    // load folded matrices once per CTA
    {
        const float4* src = (const float4*)g_A;
        float4* dst = (float4*)sm;
        for (int i = t; i < 3 * HID * HID / 4; i += NTHR) dst[i] = src[i];
    }

    // hoist per-thread constants (4 columns)
    const float4 bj = ((const float4*)g_base)[l];
    const float4 dv0 = ((const float4*)g_d)[l];
    const float4 dv1 = ((const float4*)g_d)[32 + l];
    const float4 dv2 = ((const float4*)g_d)[64 + l];

    __syncthreads();   // the only CTA-wide barrier

    const float4* vnum4 = (const float4*)g_vnum;
    const float4* Tcat4 = (const float4*)g_Tcat;

    for (int tt = blockIdx.x; tt < ntiles; tt += gridDim.x) {
        const int row0 = tt * TILE + 4 * w;

        // ---------------- embed + folded W_in : acc4[r] = h1[row0+r][4l..4l+3]
        float4 a0 = bj, a1 = bj, a2 = bj, a3 = bj;
        {
            int r0c = min(row0 + 0, nrows - 1);
            int r1c = min(row0 + 1, nrows - 1);
            int r2c = min(row0 + 2, nrows - 1);
            int r3c = min(row0 + 3, nrows - 1);
            const float* x0 = x + (size_t)r0c * 40;
            const float* x1 = x + (size_t)r1c * 40;
            const float* x2 = x + (size_t)r2c * 40;
            const float* x3 = x + (size_t)r3c * 40;
            // categorical gathers
#pragma unroll
            for (int f = 0; f < NCAT; f++) {
                int base = f * NMOD;
                float4 t0 = Tcat4[((base + (int)x0[f]) << 5) + l];
                float4 t1 = Tcat4[((base + (int)x1[f]) << 5) + l];
                float4 t2 = Tcat4[((base + (int)x2[f]) << 5) + l];
                float4 t3 = Tcat4[((base + (int)x3[f]) << 5) + l];
                a0.x += t0.x; a0.y += t0.y; a0.z += t0.z; a0.w += t0.w;
                a1.x += t1.x; a1.y += t1.y; a1.z += t1.z; a1.w += t1.w;
                a2.x += t2.x; a2.y += t2.y; a2.z += t2.z; a2.w += t2.w;
                a3.x += t3.x; a3.y += t3.y; a3.z += t3.z; a3.w += t3.w;
            }
            // numeric features
#pragma unroll
            for (int f = 0; f < NNUM; f++) {
                float4 v = vnum4[(f << 5) + l];
                float s0 = x0[NCAT + f], s1 = x1[NCAT + f];
                float s2 = x2[NCAT + f], s3 = x3[NCAT + f];
                a0.x += s0 * v.x; a0.y += s0 * v.y; a0.z += s0 * v.z; a0.w += s0 * v.w;
                a1.x += s1 * v.x; a1.y += s1 * v.y; a1.z += s1 * v.z; a1.w += s1 * v.w;
                a2.x += s2 * v.x; a2.y += s2 * v.y; a2.z += s2 * v.z; a2.w += s2 * v.w;
                a3.x += s3 * v.x; a3.y += s3 * v.y; a3.z += s3 * v.z; a3.w += s3 * v.w;
            }
        }

        // write h1 transposed into this warp's region: htw[col] = {r0,r1,r2,r3}
        htw[4 * l + 0] = make_float4(a0.x, a1.x, a2.x, a3.x);
        htw[4 * l + 1] = make_float4(a0.y, a1.y, a2.y, a3.y);
        htw[4 * l + 2] = make_float4(a0.z, a1.z, a2.z, a3.z);
        htw[4 * l + 3] = make_float4(a0.w, a1.w, a2.w, a3.w);
        __syncwarp();

        // ---------------- 3 GEMM stages (warp-local)
#pragma unroll 1
        for (int s = 0; s < 3; s++) {
            const float4 dj = (s == 0) ? dv0 : (s == 1) ? dv1 : dv2;
            // acc4[r][c]: a0..a3 rows, components = cols
            a0 = dj; a1 = dj; a2 = dj; a3 = dj;
            const float4* As4 = (const float4*)(sm + s * HID * HID) + l;
#pragma unroll 8
            for (int k = 0; k < HID; k++) {
                float4 av = As4[k * 32];      // A[k][4l..4l+3]
                float4 hv = htw[k];           // h[rows 0..3][k] (broadcast)
                a0.x += hv.x * av.x; a0.y += hv.x * av.y; a0.z += hv.x * av.z; a0.w += hv.x * av.w;
                a1.x += hv.y * av.x; a1.y += hv.y * av.y; a1.z += hv.y * av.z; a1.w += hv.y * av.w;
                a2.x += hv.z * av.x; a2.y += hv.z * av.y; a2.z += hv.z * av.z; a2.w += hv.z * av.w;
                a3.x += hv.w * av.x; a3.y += hv.w * av.y; a3.z += hv.w * av.z; a3.w += hv.w * av.w;
            }

            if (s == 2) {
                // final: write output rows (coalesced STG.128 across lanes)
                float4* o4 = (float4*)out;
                if (row0 + 0 < nrows) o4[(size_t)(row0 + 0) * 32 + l] = a0;
                if (row0 + 1 < nrows) o4[(size_t)(row0 + 1) * 32 + l] = a1;
                if (row0 + 2 < nrows) o4[(size_t)(row0 + 2) * 32 + l] = a2;
                if (row0 + 3 < nrows) o4[(size_t)(row0 + 3) * 32 + l] = a3;
            } else {
                // LayerNorm per row via warp shuffles
                float s10 = a0.x + a0.y + a0.z + a0.w;
                float s11 = a1.x + a1.y + a1.z + a1.w;
                float s12 = a2.x + a2.y + a2.z + a2.w;
                float s13 = a3.x + a3.y + a3.z + a3.w;
                float s20 = a0.x * a0.x + a0.y * a0.y + a0.z * a0.z + a0.w * a0.w;
                float s21 = a1.x * a1.x + a1.y * a1.y + a1.z * a1.z + a1.w * a1.w;
                float s22 = a2.x * a2.x + a2.y * a2.y + a2.z * a2.z + a2.w * a2.w;
                float s23 = a3.x * a3.x + a3.y * a3.y + a3.z * a3.z + a3.w * a3.w;
#pragma unroll
                for (int off = 16; off; off >>= 1) {
                    s10 += __shfl_xor_sync(0xffffffffu, s10, off);
                    s11 += __shfl_xor_sync(0xffffffffu, s11, off);
                    s12 += __shfl_xor_sync(0xffffffffu, s12, off);
                    s13 += __shfl_xor_sync(0xffffffffu, s13, off);
                    s20 += __shfl_xor_sync(0xffffffffu, s20, off);
                    s21 += __shfl_xor_sync(0xffffffffu, s21, off);
                    s22 += __shfl_xor_sync(0xffffffffu, s22, off);
                    s23 += __shfl_xor_sync(0xffffffffu, s23, off);
                }
                const float inv = 1.f / HID;
                float m0 = s10 * inv, m1 = s11 * inv, m2 = s12 * inv, m3 = s13 * inv;
                float r0 = rsqrtf(s20 * inv - m0 * m0 + 1e-5f);
                float r1 = rsqrtf(s21 * inv - m1 * m1 + 1e-5f);
                float r2 = rsqrtf(s22 * inv - m2 * m2 + 1e-5f);
                float r3 = rsqrtf(s23 * inv - m3 * m3 + 1e-5f);
                a0.x = (a0.x - m0) * r0; a0.y = (a0.y - m0) * r0; a0.z = (a0.z - m0) * r0; a0.w = (a0.w - m0) * r0;
                a1.x = (a1.x - m1) * r1; a1.y = (a1.y - m1) * r1; a1.z = (a1.z - m1) * r1; a1.w = (a1.w - m1) * r1;
                a2.x = (a2.x - m2) * r2; a2.y = (a2.y - m2) * r2; a2.z = (a2.z - m2) * r2; a2.w = (a2.w - m2) * r2;
                a3.x = (a3.x - m3) * r3; a3.y = (a3.y - m3) * r3; a3.z = (a3.z - m3) * r3; a3.w = (a3.w - m3) * r3;
                __syncwarp();   // all reads of htw done before overwrite
                htw[4 * l + 0] = make_float4(a0.x, a1.x, a2.x, a3.x);
                htw[4 * l + 1] = make_float4(a0.y, a1.y, a2.y, a3.y);
                htw[4 * l + 2] = make_float4(a0.z, a1.z, a2.z, a3.z);
                htw[4 * l + 3] = make_float4(a0.w, a1.w, a2.w, a3.w);
                __syncwarp();
            }
        }
        __syncwarp();   // htw reads complete before next tile's embed overwrites
    }
}

// ---------------- launch ----------------
extern "C" void kernel_launch(void* const* d_in, const int* in_sizes, int n_in,
                              void* d_out, int out_size) {
    const float* x     = (const float*)d_in[0];
    const float* emb   = (const float*)d_in[1];
    const float* W_num = (const float*)d_in[2];
    const float* b_num = (const float*)d_in[3];
    const float* W_in  = (const float*)d_in[4];
    const float* b_in  = (const float*)d_in[5];
    const float* W1    = (const float*)d_in[6];
    const float* b1    = (const float*)d_in[7];
    const float* W2    = (const float*)d_in[8];
    const float* b2    = (const float*)d_in[9];
    const float* ln_g  = (const float*)d_in[10];
    const float* ln_b  = (const float*)d_in[11];
    const float* W_out = (const float*)d_in[12];
    const float* b_out = (const float*)d_in[13];
    float* out = (float*)d_out;

    const int nrows  = in_sizes[0] / 40;
    const int ntiles = (nrows + TILE - 1) / TILE;
    const int smem_bytes = SM_TOTALF * (int)sizeof(float);   // 229376

    static int smem_set = 0;
    if (!smem_set) {
        cudaFuncSetAttribute(main_kernel, cudaFuncAttributeMaxDynamicSharedMemorySize,
                             smem_bytes);
        smem_set = 1;
    }

    pre_tcat_kernel<<<NCAT * NMOD, HID>>>(emb, W_in);
    pre_A_kernel<<<3 * HID, HID>>>(W1, W2, ln_g, W_out);
    pre_vec_kernel<<<1, HID>>>(W_num, b_num, W_in, b_in, W1, b1, W2, b2,
                               ln_g, ln_b, W_out, b_out);
    main_kernel<<<148, NTHR, smem_bytes>>>(x, out, nrows, ntiles);
}

// round 4
// speedup vs baseline: 2.5474x; 1.0315x over previous
#include <cuda_runtime.h>

#define NCAT 20
#define NNUM 20
#define EMBD 32
#define HID  128
#define NMOD 50
#define TILE 64            // 8 warps * 8 rows
#define NTHR 256

typedef unsigned long long u64;

// ---------------- f32x2 helpers (Blackwell packed fp32) ----------------
__device__ __forceinline__ u64 pk2(float lo, float hi) {
    u64 r; asm("mov.b64 %0,{%1,%2};" : "=l"(r) : "f"(lo), "f"(hi)); return r;
}
__device__ __forceinline__ float2 upk2(u64 v) {
    float2 f; asm("mov.b64 {%0,%1},%2;" : "=f"(f.x), "=f"(f.y) : "l"(v)); return f;
}
__device__ __forceinline__ u64 dup2(float a) {
    u64 r; asm("mov.b64 %0,{%1,%1};" : "=l"(r) : "f"(a)); return r;
}
__device__ __forceinline__ u64 fma2(u64 a, u64 b, u64 c) {
    u64 d; asm("fma.rn.f32x2 %0,%1,%2,%3;" : "=l"(d) : "l"(a), "l"(b), "l"(c)); return d;
}
__device__ __forceinline__ u64 add2(u64 a, u64 b) {
    u64 d; asm("add.rn.f32x2 %0,%1,%2;" : "=l"(d) : "l"(a), "l"(b)); return d;
}
__device__ __forceinline__ u64 mul2(u64 a, u64 b) {
    u64 d; asm("mul.rn.f32x2 %0,%1,%2;" : "=l"(d) : "l"(a), "l"(b)); return d;
}
// smem u2-index swizzle: spreads transposed stores across banks
__device__ __forceinline__ int swz(int i) { return i ^ ((i >> 3) & 7); }

// ---------------- device scratch ----------------
__device__ float g_Tcat[NCAT * NMOD * HID];
__device__ float g_A[3 * HID * HID];
__device__ float g_vnum[NNUM * HID];
__device__ float g_base[HID];
__device__ float g_d[3 * HID];

// ---------------- single merged precompute kernel ----------------
__global__ void pre_all_kernel(const float* __restrict__ emb,
                               const float* __restrict__ W_num, const float* __restrict__ b_num,
                               const float* __restrict__ W_in,  const float* __restrict__ b_in,
                               const float* __restrict__ W1,    const float* __restrict__ b1,
                               const float* __restrict__ W2,    const float* __restrict__ b2,
                               const float* __restrict__ ln_g,  const float* __restrict__ ln_b,
                               const float* __restrict__ W_out, const float* __restrict__ b_out) {
    const int b = blockIdx.x;
    const int j = threadIdx.x;
    if (b < NCAT * NMOD) {                       // --- Tcat fold ---
        int fc = b, f = fc / NMOD;
        const float* e = emb + fc * EMBD;
        float s = 0.f;
#pragma unroll
        for (int k = 0; k < EMBD; k++)
            s += e[k] * W_in[(f * EMBD + k) * HID + j];
        g_Tcat[fc * HID + j] = s;
    } else if (b < NCAT * NMOD + 3 * HID) {      // --- A matrices ---
        int bx = b - NCAT * NMOD;
        int s = bx >> 7, k = bx & 127;
        float v;
        if (s == 2) {
            v = ln_g[HID + k] * W_out[k * HID + j];
        } else {
            const float* w1 = W1 + s * HID * 2 * HID + k * 2 * HID;
            const float* w2 = W2 + s * 2 * HID * HID;
            float acc = 0.f;
            for (int m = 0; m < 2 * HID; m++) acc += w1[m] * w2[m * HID + j];
            v = (s == 1) ? ln_g[k] * acc : acc;
        }
        g_A[bx * HID + j] = v;
    } else {                                      // --- vectors ---
        for (int f = 0; f < NNUM; f++) {
            float s = 0.f;
#pragma unroll
            for (int k = 0; k < EMBD; k++)
                s += W_num[f * EMBD + k] * W_in[((NCAT + f) * EMBD + k) * HID + j];
            g_vnum[f * HID + j] = s;
        }
        float bb = b_in[j];
        for (int f = 0; f < NNUM; f++)
#pragma unroll
            for (int k = 0; k < EMBD; k++)
                bb += b_num[f * EMBD + k] * W_in[((NCAT + f) * EMBD + k) * HID + j];
        g_base[j] = bb;
        float d1 = b2[j];
        for (int m = 0; m < 2 * HID; m++) d1 += b1[m] * W2[m * HID + j];
        g_d[j] = d1;
        __shared__ float u[2 * HID];
        for (int m = j; m < 2 * HID; m += HID) {
            float s = 0.f;
            for (int k = 0; k < HID; k++)
                s += ln_b[k] * W1[HID * 2 * HID + k * 2 * HID + m];
            u[m] = s;
        }
        __syncthreads();
        float d2 = b2[HID + j];
        for (int m = 0; m < 2 * HID; m++)
            d2 += (u[m] + b1[2 * HID + m]) * W2[2 * HID * HID + m * HID + j];
        g_d[HID + j] = d2;
        float d3 = b_out[j];
        for (int k = 0; k < HID; k++) d3 += ln_b[HID + k] * W_out[k * HID + j];
        g_d[2 * HID + j] = d3;
    }
}

// ---------------- main fused kernel ----------------
// smem: A (3*128*128 f = 192KB) + per-warp htw (128 k * 2 ulonglong2, swizzled) = 4KB*8
#define SM_HT     (3 * HID * HID)                 // float offset 49152
#define SM_TOTALF (SM_HT + 8 * HID * 8)           // + 8192 floats -> 229376 B

__global__ __launch_bounds__(NTHR, 1)
void main_kernel(const float* __restrict__ x, float* __restrict__ out,
                 int nrows, int ntiles) {
    extern __shared__ float sm[];
    const int t = threadIdx.x;
    const int l = t & 31;          // lane: cols 4l..4l+3
    const int w = t >> 5;          // warp: rows 8w..8w+7 of tile

    ulonglong2* htw = (ulonglong2*)(sm + SM_HT) + w * 256;   // 256 u2 per warp

    // load folded matrices once per CTA
    {
        const float4* src = (const float4*)g_A;
        float4* dst = (float4*)sm;
        for (int i = t; i < 3 * HID * HID / 4; i += NTHR) dst[i] = src[i];
    }

    // per-thread constants
    const u64 bp0 = ((const u64*)g_base)[2 * l];
    const u64 bp1 = ((const u64*)g_base)[2 * l + 1];
    const float4 dv0 = ((const float4*)g_d)[l];
    const float4 dv1 = ((const float4*)g_d)[32 + l];
    const float4 dv2 = ((const float4*)g_d)[64 + l];
    const u64 inv2 = dup2(1.f / HID);

    __syncthreads();   // only CTA-wide barrier

    const ulonglong2* Tcat2 = (const ulonglong2*)g_Tcat;
    const ulonglong2* vnum2 = (const ulonglong2*)g_vnum;
    const float4* As4base = (const float4*)sm;

    for (int tt = blockIdx.x; tt < ntiles; tt += gridDim.x) {
        const int row0 = tt * TILE + 8 * w;

        // ---------------- embed + folded W_in (col-pair packed) ----------------
        u64 e0[8], e1[8];          // e0[r] = cols(4l,4l+1), e1[r] = cols(4l+2,4l+3)
#pragma unroll
        for (int r = 0; r < 8; r++) { e0[r] = bp0; e1[r] = bp1; }
        {
            const float* xr[8];
#pragma unroll
            for (int r = 0; r < 8; r++)
                xr[r] = x + (size_t)min(row0 + r, nrows - 1) * 40;
#pragma unroll
            for (int f = 0; f < NCAT; f++) {
                int base = f * NMOD;
#pragma unroll
                for (int r = 0; r < 8; r++) {
                    ulonglong2 tp = Tcat2[((base + (int)xr[r][f]) << 5) + l];
                    e0[r] = add2(e0[r], tp.x);
                    e1[r] = add2(e1[r], tp.y);
                }
            }
#pragma unroll
            for (int f = 0; f < NNUM; f++) {
                ulonglong2 vp = vnum2[(f << 5) + l];
#pragma unroll
                for (int r = 0; r < 8; r++) {
                    u64 d = dup2(xr[r][NCAT + f]);
                    e0[r] = fma2(vp.x, d, e0[r]);
                    e1[r] = fma2(vp.y, d, e1[r]);
                }
            }
        }
        // transpose-store h1 into htw: htw[swz(2k+p)], k = 4l+c
        {
            float ec[8][4];
#pragma unroll
            for (int r = 0; r < 8; r++) {
                float2 a = upk2(e0[r]), b = upk2(e1[r]);
                ec[r][0] = a.x; ec[r][1] = a.y; ec[r][2] = b.x; ec[r][3] = b.y;
            }
#pragma unroll
            for (int c = 0; c < 4; c++) {
                ulonglong2 v0, v1;
                v0.x = pk2(ec[0][c], ec[1][c]); v0.y = pk2(ec[2][c], ec[3][c]);
                v1.x = pk2(ec[4][c], ec[5][c]); v1.y = pk2(ec[6][c], ec[7][c]);
                htw[swz(2 * (4 * l + c) + 0)] = v0;
                htw[swz(2 * (4 * l + c) + 1)] = v1;
            }
        }
        __syncwarp();

        // ---------------- 3 GEMM stages (warp-local, f32x2) ----------------
        u64 acc[4][4];   // [rowpair 01/23/45/67][col]
#pragma unroll 1
        for (int s = 0; s < 3; s++) {
            {
                const float4 dj = (s == 0) ? dv0 : (s == 1) ? dv1 : dv2;
                u64 i0 = dup2(dj.x), i1 = dup2(dj.y), i2 = dup2(dj.z), i3 = dup2(dj.w);
#pragma unroll
                for (int rp = 0; rp < 4; rp++) {
                    acc[rp][0] = i0; acc[rp][1] = i1; acc[rp][2] = i2; acc[rp][3] = i3;
                }
            }
            const float4* As4 = As4base + s * (HID * HID / 4) + l;
#pragma unroll 4
            for (int k = 0; k < HID; k++) {
                float4 av = As4[k * 32];
                ulonglong2 hA = htw[swz(2 * k)];
                ulonglong2 hB = htw[swz(2 * k + 1)];
                u64 d0 = dup2(av.x), d1 = dup2(av.y), d2 = dup2(av.z), d3 = dup2(av.w);
                acc[0][0] = fma2(hA.x, d0, acc[0][0]);
                acc[1][0] = fma2(hA.y, d0, acc[1][0]);
                acc[2][0] = fma2(hB.x, d0, acc[2][0]);
                acc[3][0] = fma2(hB.y, d0, acc[3][0]);
                acc[0][1] = fma2(hA.x, d1, acc[0][1]);
                acc[1][1] = fma2(hA.y, d1, acc[1][1]);
                acc[2][1] = fma2(hB.x, d1, acc[2][1]);
                acc[3][1] = fma2(hB.y, d1, acc[3][1]);
                acc[0][2] = fma2(hA.x, d2, acc[0][2]);
                acc[1][2] = fma2(hA.y, d2, acc[1][2]);
                acc[2][2] = fma2(hB.x, d2, acc[2][2]);
                acc[3][2] = fma2(hB.y, d2, acc[3][2]);
                acc[0][3] = fma2(hA.x, d3, acc[0][3]);
                acc[1][3] = fma2(hA.y, d3, acc[1][3]);
                acc[2][3] = fma2(hB.x, d3, acc[2][3]);
                acc[3][3] = fma2(hB.y, d3, acc[3][3]);
            }

            if (s == 2) {
                // output: rows row0..row0+7, cols 4l..4l+3 (STG.128)
                float4* o4 = (float4*)out;
#pragma unroll
                for (int rp = 0; rp < 4; rp++) {
                    float2 c0 = upk2(acc[rp][0]), c1 = upk2(acc[rp][1]);
                    float2 c2 = upk2(acc[rp][2]), c3 = upk2(acc[rp][3]);
                    int ra = row0 + 2 * rp, rb = ra + 1;
                    if (ra < nrows)
                        o4[(size_t)ra * 32 + l] = make_float4(c0.x, c1.x, c2.x, c3.x);
                    if (rb < nrows)
                        o4[(size_t)rb * 32 + l] = make_float4(c0.y, c1.y, c2.y, c3.y);
                }
            } else {
                // ---- LayerNorm per row (packed row-pairs, warp shuffles) ----
#pragma unroll
                for (int rp = 0; rp < 4; rp++) {
                    u64 s1 = add2(add2(acc[rp][0], acc[rp][1]),
                                  add2(acc[rp][2], acc[rp][3]));
                    u64 s2 = fma2(acc[rp][0], acc[rp][0],
                             fma2(acc[rp][1], acc[rp][1],
                             fma2(acc[rp][2], acc[rp][2],
                             mul2(acc[rp][3], acc[rp][3]))));
#pragma unroll
                    for (int off = 16; off; off >>= 1) {
                        s1 = add2(s1, __shfl_xor_sync(0xffffffffu, s1, off));
                        s2 = add2(s2, __shfl_xor_sync(0xffffffffu, s2, off));
                    }
                    float2 m = upk2(mul2(s1, inv2));
                    float2 q = upk2(mul2(s2, inv2));
                    float r0 = rsqrtf(q.x - m.x * m.x + 1e-5f);
                    float r1 = rsqrtf(q.y - m.y * m.y + 1e-5f);
                    u64 rr  = pk2(r0, r1);
                    u64 nmr = pk2(-m.x * r0, -m.y * r1);
#pragma unroll
                    for (int c = 0; c < 4; c++)
                        acc[rp][c] = fma2(acc[rp][c], rr, nmr);
                }
                __syncwarp();   // reads of htw done before overwrite
#pragma unroll
                for (int c = 0; c < 4; c++) {
                    ulonglong2 v0, v1;
                    v0.x = acc[0][c]; v0.y = acc[1][c];
                    v1.x = acc[2][c]; v1.y = acc[3][c];
                    htw[swz(2 * (4 * l + c) + 0)] = v0;
                    htw[swz(2 * (4 * l + c) + 1)] = v1;
                }
                __syncwarp();
            }
        }
        __syncwarp();   // htw reads complete before next tile overwrites
    }
}

// ---------------- launch ----------------
extern "C" void kernel_launch(void* const* d_in, const int* in_sizes, int n_in,
                              void* d_out, int out_size) {
    const float* x     = (const float*)d_in[0];
    const float* emb   = (const float*)d_in[1];
    const float* W_num = (const float*)d_in[2];
    const float* b_num = (const float*)d_in[3];
    const float* W_in  = (const float*)d_in[4];
    const float* b_in  = (const float*)d_in[5];
    const float* W1    = (const float*)d_in[6];
    const float* b1    = (const float*)d_in[7];
    const float* W2    = (const float*)d_in[8];
    const float* b2    = (const float*)d_in[9];
    const float* ln_g  = (const float*)d_in[10];
    const float* ln_b  = (const float*)d_in[11];
    const float* W_out = (const float*)d_in[12];
    const float* b_out = (const float*)d_in[13];
    float* out = (float*)d_out;

    const int nrows  = in_sizes[0] / 40;
    const int ntiles = (nrows + TILE - 1) / TILE;
    const int smem_bytes = SM_TOTALF * (int)sizeof(float);   // 229376

    static int smem_set = 0;
    if (!smem_set) {
        cudaFuncSetAttribute(main_kernel, cudaFuncAttributeMaxDynamicSharedMemorySize,
                             smem_bytes);
        smem_set = 1;
    }

    pre_all_kernel<<<NCAT * NMOD + 3 * HID + 1, HID>>>(
        emb, W_num, b_num, W_in, b_in, W1, b1, W2, b2, ln_g, ln_b, W_out, b_out);
    main_kernel<<<148, NTHR, smem_bytes>>>(x, out, nrows, ntiles);
}